// round 9
// baseline (speedup 1.0000x reference)
#include <cuda_runtime.h>
#include <math.h>

#define N_NODES 10000
#define K_NBR   32
#define C_DIM   64
#define H_DIM   64
#define ALPHA   0.3f
#define NITER   4

typedef unsigned long long u64;

// Intermediates (static device arrays -> L2-resident):
// g_H[n][h] = leaky(embs[n] @ Q_w + Q_b)        2.56 MB
// g_P[n][h] = embs[n] @ W_top + W_b             2.56 MB
__device__ float g_H[N_NODES * H_DIM];
__device__ float g_P[N_NODES * H_DIM];

__device__ __forceinline__ u64 pack2(float x) {
    u64 r; asm("mov.b64 %0, {%1, %1};" : "=l"(r) : "f"(x)); return r;
}
__device__ __forceinline__ void ffma2(u64& d, u64 a, u64 b) {
    asm("fma.rn.f32x2 %0, %1, %2, %0;" : "+l"(d) : "l"(a), "l"(b));
}
__device__ __forceinline__ float2 unpack2(u64 v) {
    float2 f; asm("mov.b64 {%0, %1}, %2;" : "=f"(f.x), "=f"(f.y) : "l"(v)); return f;
}
__device__ __forceinline__ float leaky(float x) { return x >= 0.f ? x : ALPHA * x; }

// ---------------------------------------------------------------------------
// Kernel A: per node, two 64x64 GEMVs over embs:
//   g_H = leaky(embs @ Q_w + Q_b),  g_P = embs @ W_w[0:64] + W_b
// block = 256 (8 warps), 2 nodes/warp, grid = 625 (exact).
// ---------------------------------------------------------------------------
__global__ __launch_bounds__(256) void qproj_kernel(const float* __restrict__ embs,
                                                    const float* __restrict__ Qw,
                                                    const float* __restrict__ Qb,
                                                    const float* __restrict__ Ww,
                                                    const float* __restrict__ Wb) {
    __shared__ float2 sQ[C_DIM * 32];   // sQ[c*32+l] = (Qw[c][2l], Qw[c][2l+1])
    __shared__ float2 sP[C_DIM * 32];   // W_top rows 0..63 of Ww
    __shared__ float  sE[8][2][C_DIM];

    const int tid  = threadIdx.x;
    const int lane = tid & 31;
    const int warp = tid >> 5;

    const float2* Q2 = (const float2*)Qw;
    const float2* W2 = (const float2*)Ww;
    for (int i = tid; i < C_DIM * 32; i += 256) { sQ[i] = Q2[i]; sP[i] = W2[i]; }
    __syncthreads();

    const int n0 = blockIdx.x * 16 + warp * 2;   // exact, no clamp
#pragma unroll
    for (int i = 0; i < 2; ++i) {
        float2 e = ((const float2*)embs)[(n0 + i) * 32 + lane];
        *(float2*)&sE[warp][i][2 * lane] = e;
    }
    __syncwarp();

    const u64 qb = ((const u64*)Qb)[lane];
    const u64 wb = ((const u64*)Wb)[lane];
    u64 aq[2] = {qb, qb}, ap[2] = {wb, wb};

    const u64* sQ64 = (const u64*)sQ;
    const u64* sP64 = (const u64*)sP;
#pragma unroll
    for (int c = 0; c < C_DIM; c += 4) {
        u64 q0 = sQ64[(c + 0) * 32 + lane], p0 = sP64[(c + 0) * 32 + lane];
        u64 q1 = sQ64[(c + 1) * 32 + lane], p1 = sP64[(c + 1) * 32 + lane];
        u64 q2 = sQ64[(c + 2) * 32 + lane], p2 = sP64[(c + 2) * 32 + lane];
        u64 q3 = sQ64[(c + 3) * 32 + lane], p3 = sP64[(c + 3) * 32 + lane];
#pragma unroll
        for (int i = 0; i < 2; ++i) {
            float4 x = *(const float4*)&sE[warp][i][c];
            u64 x0 = pack2(x.x), x1 = pack2(x.y), x2 = pack2(x.z), x3 = pack2(x.w);
            ffma2(aq[i], x0, q0); ffma2(ap[i], x0, p0);
            ffma2(aq[i], x1, q1); ffma2(ap[i], x1, p1);
            ffma2(aq[i], x2, q2); ffma2(ap[i], x2, p2);
            ffma2(aq[i], x3, q3); ffma2(ap[i], x3, p3);
        }
    }

#pragma unroll
    for (int i = 0; i < 2; ++i) {
        float2 h = unpack2(aq[i]);
        h.x = leaky(h.x); h.y = leaky(h.y);
        ((float2*)g_H)[(n0 + i) * 32 + lane] = h;
        ((float2*)g_P)[(n0 + i) * 32 + lane] = unpack2(ap[i]);
    }
}

// ---------------------------------------------------------------------------
// Kernel B (fused, software-pipelined): each warp processes NITER=4 nodes.
// Per iteration t: issue random weights load for t+1 and nbr load for t+2
// (both land during node t's gather+GEMM), then compute node t:
//   wsh = sum_k w_k * g_H[j_k] / (sum w + 1e-6)
//   out = normalize(leaky(g_P[n] + wsh @ W_w[64:128]))
// block = 256 (8 warps), grid = 313 (313*8*4 = 10016, clamped+guarded).
// ---------------------------------------------------------------------------
__global__ __launch_bounds__(256) void agg_kernel(const float* __restrict__ weights,
                                                  const int*   __restrict__ nbr,
                                                  const float* __restrict__ Ww,
                                                  float* __restrict__ out) {
    __shared__ float2 sV[H_DIM * 32];   // W_bot rows 64..127, (W[c][2l], W[c][2l+1])
    __shared__ float2 sJW[8][K_NBR];    // per-warp (w_k, bitcast j_k) for current node
    __shared__ float  sX[8][H_DIM];     // per-warp weighted-mean-hidden vector

    const int tid  = threadIdx.x;
    const int lane = tid & 31;
    const int warp = tid >> 5;

    const float2* W2 = (const float2*)Ww;
    for (int i = tid; i < H_DIM * 32; i += 256) sV[i] = W2[2048 + i];  // rows 64..127
    __syncthreads();

    const int gw = blockIdx.x * 8 + warp;          // global warp id, 0..2503
    int n[NITER];
#pragma unroll
    for (int t = 0; t < NITER; ++t) n[t] = min(gw * NITER + t, N_NODES - 1);

    // pipeline prologue: j for t=0,1 ; w for t=0
    int   jA = nbr[n[0] * K_NBR + lane];
    float wA = __ldcs(&weights[(size_t)n[0] * N_NODES + jA]);
    int   jB = nbr[n[1] * K_NBR + lane];

    const u64* H2 = (const u64*)g_H;
    const u64* P2 = (const u64*)g_P;
    const u64* sV64 = (const u64*)sV;

#pragma unroll
    for (int t = 0; t < NITER; ++t) {
        // ---- prefetch for future iterations (latency hidden behind compute) ----
        float wB = 0.f;
        int   jC = 0;
        if (t + 1 < NITER) wB = __ldcs(&weights[(size_t)n[t + 1] * N_NODES + jB]);
        if (t + 2 < NITER) jC = nbr[n[t + 2] * K_NBR + lane];

        // ---- compute node n[t] with (jA, wA) ----
        __syncwarp();                        // prior iter's sJW/sX reads done
        sJW[warp][lane] = make_float2(wA, __int_as_float(jA));

        float ws = wA;
#pragma unroll
        for (int o = 16; o; o >>= 1) ws += __shfl_xor_sync(0xffffffffu, ws, o);
        const float inv = 1.f / (ws + 1e-6f);

        u64 o_acc = P2[n[t] * 32 + lane];    // emb-projection row (L2-hot)
        __syncwarp();

        u64 acc = 0;
#pragma unroll 8
        for (int k = 0; k < K_NBR; ++k) {
            float2 jw = sJW[warp][k];        // broadcast LDS
            int j = __float_as_int(jw.y);
            ffma2(acc, pack2(jw.x), H2[j * 32 + lane]);
        }

        float2 a = unpack2(acc);
        a.x *= inv; a.y *= inv;
        *(float2*)&sX[warp][2 * lane] = a;
        __syncwarp();

        // o += wsh @ W_bot
#pragma unroll
        for (int c = 0; c < H_DIM; c += 4) {
            float4 x = *(const float4*)&sX[warp][c];
            ffma2(o_acc, pack2(x.x), sV64[(c + 0) * 32 + lane]);
            ffma2(o_acc, pack2(x.y), sV64[(c + 1) * 32 + lane]);
            ffma2(o_acc, pack2(x.z), sV64[(c + 2) * 32 + lane]);
            ffma2(o_acc, pack2(x.w), sV64[(c + 3) * 32 + lane]);
        }

        float2 f = unpack2(o_acc);
        f.x = leaky(f.x); f.y = leaky(f.y);
        float ss = f.x * f.x + f.y * f.y;
#pragma unroll
        for (int off = 16; off; off >>= 1) ss += __shfl_xor_sync(0xffffffffu, ss, off);
        const float d = 1.f / (sqrtf(ss) + 1e-6f);

        const int raw = gw * NITER + t;
        if (raw < N_NODES)
            ((float2*)out)[raw * 32 + lane] = make_float2(f.x * d, f.y * d);

        // ---- rotate pipeline registers ----
        jA = jB; wA = wB; jB = jC;
    }
}

// ---------------------------------------------------------------------------
// Inputs (metadata order):
//   0 embs (1,10000,64) f32   1 weights (10000,10000) f32
//   2 neighbor_set (10000,32) i32   3 Q_w (64,64) f32   4 Q_b (64,) f32
//   5 W_w (128,64) f32   6 W_b (64,) f32
// ---------------------------------------------------------------------------
extern "C" void kernel_launch(void* const* d_in, const int* in_sizes, int n_in,
                              void* d_out, int out_size) {
    const float* embs    = (const float*)d_in[0];
    const float* weights = (const float*)d_in[1];
    const int*   nbr     = (const int*)  d_in[2];
    const float* Qw      = (const float*)d_in[3];
    const float* Qb      = (const float*)d_in[4];
    const float* Ww      = (const float*)d_in[5];
    const float* Wb      = (const float*)d_in[6];
    float* out = (float*)d_out;

    qproj_kernel<<<625, 256>>>(embs, Qw, Qb, Ww, Wb);
    agg_kernel<<<313, 256>>>(weights, nbr, Ww, out);
}

// round 10
// speedup vs baseline: 1.2810x; 1.2810x over previous
#include <cuda_runtime.h>
#include <cuda_fp16.h>
#include <math.h>

#define N_NODES 10000
#define K_NBR   32
#define C_DIM   64
#define H_DIM   64
#define ALPHA   0.3f

typedef unsigned long long u64;

// Intermediates (static device arrays -> L2-resident):
// g_H[n][l] = fp16x2 of leaky(embs[n] @ Q_w + Q_b)     1.28 MB (halved gather bytes)
// g_P[n][h] = embs[n] @ W_top + W_b  (fp32)            2.56 MB
// g_W[n][k] = weights[n][nbr[n][k]] / (sum_k + 1e-6)   1.28 MB (pre-scaled)
__device__ __half2 g_H[N_NODES * 32];
__device__ float   g_P[N_NODES * H_DIM];
__device__ float   g_W[N_NODES * K_NBR];

__device__ __forceinline__ u64 pack2(float x) {
    u64 r; asm("mov.b64 %0, {%1, %1};" : "=l"(r) : "f"(x)); return r;
}
__device__ __forceinline__ u64 packf2(float2 v) {
    u64 r; asm("mov.b64 %0, {%1, %2};" : "=l"(r) : "f"(v.x), "f"(v.y)); return r;
}
__device__ __forceinline__ void ffma2(u64& d, u64 a, u64 b) {
    asm("fma.rn.f32x2 %0, %1, %2, %0;" : "+l"(d) : "l"(a), "l"(b));
}
__device__ __forceinline__ float2 unpack2(u64 v) {
    float2 f; asm("mov.b64 {%0, %1}, %2;" : "=f"(f.x), "=f"(f.y) : "l"(v)); return f;
}
__device__ __forceinline__ float leaky(float x) { return x >= 0.f ? x : ALPHA * x; }

// ---------------------------------------------------------------------------
// Kernel PREP (merged): 1875 blocks x 256.
//   bid % 3 == 0  -> qproj block  (qid = bid/3, 625 blocks, 16 nodes each)
//   else          -> wgather block (widx 0..1249, 8 nodes each, warp-per-node)
// Interleaving mixes DRAM-latency blocks and FMA blocks in every wave, so the
// qproj work hides inside wgather's idle issue slots.
// ---------------------------------------------------------------------------
__global__ __launch_bounds__(256) void prep_kernel(const float* __restrict__ embs,
                                                   const float* __restrict__ weights,
                                                   const int*   __restrict__ nbr,
                                                   const float* __restrict__ Qw,
                                                   const float* __restrict__ Qb,
                                                   const float* __restrict__ Ww,
                                                   const float* __restrict__ Wb) {
    __shared__ float2 sQ[C_DIM * 32];   // (Qw[c][2l], Qw[c][2l+1])
    __shared__ float2 sP[C_DIM * 32];   // W_top rows 0..63 of Ww
    __shared__ float  sE[8][2][C_DIM];

    const int bid  = blockIdx.x;
    const int tid  = threadIdx.x;
    const int lane = tid & 31;
    const int warp = tid >> 5;

    if (bid % 3 != 0) {
        // ---------------- wgather path: random weights, max MLP ----------------
        const int widx = (bid % 3 == 1) ? (bid / 3) * 2 : (bid / 3) * 2 + 1;  // 0..1249
        const int node = widx * 8 + warp;

        const int   j = nbr[node * K_NBR + lane];                      // coalesced
        const float w = __ldcs(&weights[(size_t)node * N_NODES + j]);  // random DRAM

        float ws = w;
#pragma unroll
        for (int o = 16; o; o >>= 1) ws += __shfl_xor_sync(0xffffffffu, ws, o);

        g_W[node * K_NBR + lane] = w * (1.f / (ws + 1e-6f));
        return;
    }

    // ---------------- qproj path: two 64x64 GEMVs per node ----------------
    const int qid = bid / 3;            // 0..624

    const float2* Q2 = (const float2*)Qw;
    const float2* W2 = (const float2*)Ww;
    for (int i = tid; i < C_DIM * 32; i += 256) { sQ[i] = Q2[i]; sP[i] = W2[i]; }
    __syncthreads();

    const int n0 = qid * 16 + warp * 2;   // exact: 625*16 = 10000
#pragma unroll
    for (int i = 0; i < 2; ++i) {
        float2 e = ((const float2*)embs)[(n0 + i) * 32 + lane];
        *(float2*)&sE[warp][i][2 * lane] = e;
    }
    __syncwarp();

    const u64 qb = ((const u64*)Qb)[lane];
    const u64 wb = ((const u64*)Wb)[lane];
    u64 aq[2] = {qb, qb}, ap[2] = {wb, wb};

    const u64* sQ64 = (const u64*)sQ;
    const u64* sP64 = (const u64*)sP;
#pragma unroll
    for (int c = 0; c < C_DIM; c += 4) {
        u64 q0 = sQ64[(c + 0) * 32 + lane], p0 = sP64[(c + 0) * 32 + lane];
        u64 q1 = sQ64[(c + 1) * 32 + lane], p1 = sP64[(c + 1) * 32 + lane];
        u64 q2 = sQ64[(c + 2) * 32 + lane], p2 = sP64[(c + 2) * 32 + lane];
        u64 q3 = sQ64[(c + 3) * 32 + lane], p3 = sP64[(c + 3) * 32 + lane];
#pragma unroll
        for (int i = 0; i < 2; ++i) {
            float4 x = *(const float4*)&sE[warp][i][c];
            u64 x0 = pack2(x.x), x1 = pack2(x.y), x2 = pack2(x.z), x3 = pack2(x.w);
            ffma2(aq[i], x0, q0); ffma2(ap[i], x0, p0);
            ffma2(aq[i], x1, q1); ffma2(ap[i], x1, p1);
            ffma2(aq[i], x2, q2); ffma2(ap[i], x2, p2);
            ffma2(aq[i], x3, q3); ffma2(ap[i], x3, p3);
        }
    }

#pragma unroll
    for (int i = 0; i < 2; ++i) {
        float2 h = unpack2(aq[i]);
        h.x = leaky(h.x); h.y = leaky(h.y);
        g_H[(n0 + i) * 32 + lane] = __float22half2_rn(h);   // fp16 hidden table
        ((float2*)g_P)[(n0 + i) * 32 + lane] = unpack2(ap[i]);
    }
}

// ---------------------------------------------------------------------------
// Kernel B: gather+pre-scaled-weighted-sum from fp16 g_H (L2-resident), then
//   out = normalize(leaky(g_P + wsh @ W_w[64:128]))
// block = 256 (8 warps), 2 nodes/warp, grid = 625 (exact).
// ---------------------------------------------------------------------------
__global__ __launch_bounds__(256) void agg_kernel(const int*   __restrict__ nbr,
                                                  const float* __restrict__ Ww,
                                                  float* __restrict__ out) {
    __shared__ float2 sV[H_DIM * 32];   // W_bot rows 64..127
    __shared__ float2 sJW[8][2][K_NBR]; // per-node (w'_k, bitcast j_k)
    __shared__ float  sX[8][2][H_DIM];  // per-warp weighted-sum-hidden vectors

    const int tid  = threadIdx.x;
    const int lane = tid & 31;
    const int warp = tid >> 5;

    const float2* W2 = (const float2*)Ww;
    for (int i = tid; i < H_DIM * 32; i += 256) sV[i] = W2[2048 + i];  // rows 64..127
    __syncthreads();

    const int n0 = blockIdx.x * 16 + warp * 2;   // exact, no clamp

    // coalesced, L2-hot setup loads (no random access here)
#pragma unroll
    for (int i = 0; i < 2; ++i) {
        int   j = nbr[(n0 + i) * K_NBR + lane];
        float w = g_W[(n0 + i) * K_NBR + lane];   // pre-scaled
        sJW[warp][i][lane] = make_float2(w, __int_as_float(j));
    }

    // prefetch the emb-projection rows early (overlaps with gather)
    u64 o[2];
    const u64* P2 = (const u64*)g_P;
#pragma unroll
    for (int i = 0; i < 2; ++i) o[i] = P2[(n0 + i) * 32 + lane];
    __syncwarp();

    // gather + weighted accumulate: 1 LDG.32 (half2) per (node,k) per lane
    u64 acc[2] = {0, 0};
#pragma unroll 8
    for (int k = 0; k < K_NBR; ++k) {
#pragma unroll
        for (int i = 0; i < 2; ++i) {
            float2 jw = sJW[warp][i][k];           // broadcast LDS
            int j = __float_as_int(jw.y);
            float2 hf = __half22float2(g_H[j * 32 + lane]);
            ffma2(acc[i], pack2(jw.x), packf2(hf));
        }
    }

    // stage weighted-sum-hidden into shared for float4 broadcast reads
#pragma unroll
    for (int i = 0; i < 2; ++i)
        *(float2*)&sX[warp][i][2 * lane] = unpack2(acc[i]);
    __syncwarp();

    // o += wsh @ W_bot
    const u64* sV64 = (const u64*)sV;
#pragma unroll
    for (int c = 0; c < H_DIM; c += 4) {
        u64 v0 = sV64[(c + 0) * 32 + lane];
        u64 v1 = sV64[(c + 1) * 32 + lane];
        u64 v2 = sV64[(c + 2) * 32 + lane];
        u64 v3 = sV64[(c + 3) * 32 + lane];
#pragma unroll
        for (int i = 0; i < 2; ++i) {
            float4 x = *(const float4*)&sX[warp][i][c];
            ffma2(o[i], pack2(x.x), v0);
            ffma2(o[i], pack2(x.y), v1);
            ffma2(o[i], pack2(x.z), v2);
            ffma2(o[i], pack2(x.w), v3);
        }
    }

    // leaky + L2-normalize + store
#pragma unroll
    for (int i = 0; i < 2; ++i) {
        float2 f = unpack2(o[i]);
        f.x = leaky(f.x); f.y = leaky(f.y);
        float ss = f.x * f.x + f.y * f.y;
#pragma unroll
        for (int off = 16; off; off >>= 1) ss += __shfl_xor_sync(0xffffffffu, ss, off);
        float d = 1.f / (sqrtf(ss) + 1e-6f);
        ((float2*)out)[(n0 + i) * 32 + lane] = make_float2(f.x * d, f.y * d);
    }
}

// ---------------------------------------------------------------------------
// Inputs (metadata order):
//   0 embs (1,10000,64) f32   1 weights (10000,10000) f32
//   2 neighbor_set (10000,32) i32   3 Q_w (64,64) f32   4 Q_b (64,) f32
//   5 W_w (128,64) f32   6 W_b (64,) f32
// ---------------------------------------------------------------------------
extern "C" void kernel_launch(void* const* d_in, const int* in_sizes, int n_in,
                              void* d_out, int out_size) {
    const float* embs    = (const float*)d_in[0];
    const float* weights = (const float*)d_in[1];
    const int*   nbr     = (const int*)  d_in[2];
    const float* Qw      = (const float*)d_in[3];
    const float* Qb      = (const float*)d_in[4];
    const float* Ww      = (const float*)d_in[5];
    const float* Wb      = (const float*)d_in[6];
    float* out = (float*)d_out;

    prep_kernel<<<1875, 256>>>(embs, weights, nbr, Qw, Qb, Ww, Wb);  // wgather + qproj mixed
    agg_kernel<<<625, 256>>>(nbr, Ww, out);                          // fp16 gather + GEMM
}

// round 11
// speedup vs baseline: 1.4398x; 1.1240x over previous
#include <cuda_runtime.h>
#include <cuda_fp16.h>
#include <math.h>

#define N_NODES 10000
#define K_NBR   32
#define C_DIM   64
#define H_DIM   64
#define ALPHA   0.3f

typedef unsigned long long u64;

// Intermediates (static device arrays -> L2-resident):
// g_H[n][l] = fp16x2 of leaky(embs[n] @ Q_w + Q_b)     1.28 MB
// g_P[n][h] = embs[n] @ W_top + W_b  (fp32)            2.56 MB
__device__ __half2 g_H[N_NODES * 32];
__device__ float   g_P[N_NODES * H_DIM];

__device__ __forceinline__ u64 pack2(float x) {
    u64 r; asm("mov.b64 %0, {%1, %1};" : "=l"(r) : "f"(x)); return r;
}
__device__ __forceinline__ u64 packf2(float2 v) {
    u64 r; asm("mov.b64 %0, {%1, %2};" : "=l"(r) : "f"(v.x), "f"(v.y)); return r;
}
__device__ __forceinline__ void ffma2(u64& d, u64 a, u64 b) {
    asm("fma.rn.f32x2 %0, %1, %2, %0;" : "+l"(d) : "l"(a), "l"(b));
}
__device__ __forceinline__ float2 unpack2(u64 v) {
    float2 f; asm("mov.b64 {%0, %1}, %2;" : "=f"(f.x), "=f"(f.y) : "l"(v)); return f;
}
__device__ __forceinline__ float leaky(float x) { return x >= 0.f ? x : ALPHA * x; }

// ---------------------------------------------------------------------------
// Kernel A: per node, two 64x64 GEMVs over embs:
//   g_H = fp16(leaky(embs @ Q_w + Q_b)),  g_P = embs @ W_w[0:64] + W_b
// block = 256 (8 warps), 2 nodes/warp, grid = 625 (exact).
// ---------------------------------------------------------------------------
__global__ __launch_bounds__(256) void qproj_kernel(const float* __restrict__ embs,
                                                    const float* __restrict__ Qw,
                                                    const float* __restrict__ Qb,
                                                    const float* __restrict__ Ww,
                                                    const float* __restrict__ Wb) {
    __shared__ float2 sQ[C_DIM * 32];   // (Qw[c][2l], Qw[c][2l+1])
    __shared__ float2 sP[C_DIM * 32];   // W_top rows 0..63 of Ww
    __shared__ float  sE[8][2][C_DIM];

    const int tid  = threadIdx.x;
    const int lane = tid & 31;
    const int warp = tid >> 5;

    const float2* Q2 = (const float2*)Qw;
    const float2* W2 = (const float2*)Ww;
    for (int i = tid; i < C_DIM * 32; i += 256) { sQ[i] = Q2[i]; sP[i] = W2[i]; }
    __syncthreads();

    const int n0 = blockIdx.x * 16 + warp * 2;   // exact: 625*16 = 10000
#pragma unroll
    for (int i = 0; i < 2; ++i) {
        float2 e = ((const float2*)embs)[(n0 + i) * 32 + lane];
        *(float2*)&sE[warp][i][2 * lane] = e;
    }
    __syncwarp();

    const u64 qb = ((const u64*)Qb)[lane];
    const u64 wb = ((const u64*)Wb)[lane];
    u64 aq[2] = {qb, qb}, ap[2] = {wb, wb};

    const u64* sQ64 = (const u64*)sQ;
    const u64* sP64 = (const u64*)sP;
#pragma unroll
    for (int c = 0; c < C_DIM; c += 4) {
        u64 q0 = sQ64[(c + 0) * 32 + lane], p0 = sP64[(c + 0) * 32 + lane];
        u64 q1 = sQ64[(c + 1) * 32 + lane], p1 = sP64[(c + 1) * 32 + lane];
        u64 q2 = sQ64[(c + 2) * 32 + lane], p2 = sP64[(c + 2) * 32 + lane];
        u64 q3 = sQ64[(c + 3) * 32 + lane], p3 = sP64[(c + 3) * 32 + lane];
#pragma unroll
        for (int i = 0; i < 2; ++i) {
            float4 x = *(const float4*)&sE[warp][i][c];
            u64 x0 = pack2(x.x), x1 = pack2(x.y), x2 = pack2(x.z), x3 = pack2(x.w);
            ffma2(aq[i], x0, q0); ffma2(ap[i], x0, p0);
            ffma2(aq[i], x1, q1); ffma2(ap[i], x1, p1);
            ffma2(aq[i], x2, q2); ffma2(ap[i], x2, p2);
            ffma2(aq[i], x3, q3); ffma2(ap[i], x3, p3);
        }
    }

#pragma unroll
    for (int i = 0; i < 2; ++i) {
        float2 h = unpack2(aq[i]);
        h.x = leaky(h.x); h.y = leaky(h.y);
        g_H[(n0 + i) * 32 + lane] = __float22half2_rn(h);
        ((float2*)g_P)[(n0 + i) * 32 + lane] = unpack2(ap[i]);
    }
}

// ---------------------------------------------------------------------------
// Kernel B (fused): random weights gather + weighted fp16-hidden gather + GEMM.
// Critical ordering: random __ldcs loads issue FIRST; the 16 KB sV fill,
// g_P prefetch and barrier sit between issue and first consumption, covering
// the DRAM latency. Resident blocks stagger the rest.
// block = 256 (8 warps), 2 nodes/warp, grid = 625 (exact).
// ---------------------------------------------------------------------------
__global__ __launch_bounds__(256) void agg_kernel(const float* __restrict__ weights,
                                                  const int*   __restrict__ nbr,
                                                  const float* __restrict__ Ww,
                                                  float* __restrict__ out) {
    __shared__ float2 sV[H_DIM * 32];   // W_bot rows 64..127
    __shared__ float2 sJW[8][2][K_NBR]; // per-node (w'_k prescaled, bitcast j_k)
    __shared__ float  sX[8][2][H_DIM];  // per-warp weighted-sum-hidden vectors

    const int tid  = threadIdx.x;
    const int lane = tid & 31;
    const int warp = tid >> 5;

    const int n0 = blockIdx.x * 16 + warp * 2;   // exact, no clamp

    // ---- 1) indices + 2) issue random DRAM loads immediately ----
    int   jj[2];
    float wt[2];
#pragma unroll
    for (int i = 0; i < 2; ++i) jj[i] = nbr[(n0 + i) * K_NBR + lane];
#pragma unroll
    for (int i = 0; i < 2; ++i)
        wt[i] = __ldcs(&weights[(size_t)(n0 + i) * N_NODES + jj[i]]);  // in flight...

    // ---- 3) cover the latency: fill sV (16 KB) + prefetch g_P rows ----
    const float2* W2 = (const float2*)Ww;
    for (int i = tid; i < H_DIM * 32; i += 256) sV[i] = W2[2048 + i];  // rows 64..127

    u64 o[2];
    const u64* P2 = (const u64*)g_P;
#pragma unroll
    for (int i = 0; i < 2; ++i) o[i] = P2[(n0 + i) * 32 + lane];
    __syncthreads();                               // sV ready; w loads have aged

    // ---- 4) consume random weights: reduce, prescale, stage ----
#pragma unroll
    for (int i = 0; i < 2; ++i) {
        float ws = wt[i];
#pragma unroll
        for (int off = 16; off; off >>= 1) ws += __shfl_xor_sync(0xffffffffu, ws, off);
        float inv = 1.f / (ws + 1e-6f);
        sJW[warp][i][lane] = make_float2(wt[i] * inv, __int_as_float(jj[i]));
    }
    __syncwarp();

    // ---- 5) fp16 gather + weighted accumulate (g_H L2-resident) ----
    u64 acc[2] = {0, 0};
#pragma unroll 8
    for (int k = 0; k < K_NBR; ++k) {
#pragma unroll
        for (int i = 0; i < 2; ++i) {
            float2 jw = sJW[warp][i][k];           // broadcast LDS
            int j = __float_as_int(jw.y);
            float2 hf = __half22float2(g_H[j * 32 + lane]);
            ffma2(acc[i], pack2(jw.x), packf2(hf));
        }
    }

#pragma unroll
    for (int i = 0; i < 2; ++i)
        *(float2*)&sX[warp][i][2 * lane] = unpack2(acc[i]);
    __syncwarp();

    // ---- 6) o += wsh @ W_bot ----
    const u64* sV64 = (const u64*)sV;
#pragma unroll
    for (int c = 0; c < H_DIM; c += 4) {
        u64 v0 = sV64[(c + 0) * 32 + lane];
        u64 v1 = sV64[(c + 1) * 32 + lane];
        u64 v2 = sV64[(c + 2) * 32 + lane];
        u64 v3 = sV64[(c + 3) * 32 + lane];
#pragma unroll
        for (int i = 0; i < 2; ++i) {
            float4 x = *(const float4*)&sX[warp][i][c];
            ffma2(o[i], pack2(x.x), v0);
            ffma2(o[i], pack2(x.y), v1);
            ffma2(o[i], pack2(x.z), v2);
            ffma2(o[i], pack2(x.w), v3);
        }
    }

    // ---- 7) leaky + L2-normalize + store ----
#pragma unroll
    for (int i = 0; i < 2; ++i) {
        float2 f = unpack2(o[i]);
        f.x = leaky(f.x); f.y = leaky(f.y);
        float ss = f.x * f.x + f.y * f.y;
#pragma unroll
        for (int off = 16; off; off >>= 1) ss += __shfl_xor_sync(0xffffffffu, ss, off);
        float d = 1.f / (sqrtf(ss) + 1e-6f);
        ((float2*)out)[(n0 + i) * 32 + lane] = make_float2(f.x * d, f.y * d);
    }
}

// ---------------------------------------------------------------------------
// Inputs (metadata order):
//   0 embs (1,10000,64) f32   1 weights (10000,10000) f32
//   2 neighbor_set (10000,32) i32   3 Q_w (64,64) f32   4 Q_b (64,) f32
//   5 W_w (128,64) f32   6 W_b (64,) f32
// ---------------------------------------------------------------------------
extern "C" void kernel_launch(void* const* d_in, const int* in_sizes, int n_in,
                              void* d_out, int out_size) {
    const float* embs    = (const float*)d_in[0];
    const float* weights = (const float*)d_in[1];
    const int*   nbr     = (const int*)  d_in[2];
    const float* Qw      = (const float*)d_in[3];
    const float* Qb      = (const float*)d_in[4];
    const float* Ww      = (const float*)d_in[5];
    const float* Wb      = (const float*)d_in[6];
    float* out = (float*)d_out;

    qproj_kernel<<<625, 256>>>(embs, Qw, Qb, Ww, Wb);
    agg_kernel<<<625, 256>>>(weights, nbr, Ww, out);
}